// round 12
// baseline (speedup 1.0000x reference)
#include <cuda_runtime.h>
#include <math.h>

#define B_   4
#define S_   4096
#define D_   768
#define H_   12
#define DH_  64
#define BS_  64
#define L_   2
#define R_   3
#define FF_  3072
#define NB_  64
#define NSEL_ 8
#define D3_  2304
#define M_   (B_*S_)

// ---------------- scratch (static device globals; no allocation) ----------------
__device__ float g_h   [(size_t)M_*D_];   // hidden state            [B*S, D]
__device__ float g_qkv [(size_t)M_*D3_];  // qkv projection          [B*S, 3D]
__device__ float g_attn[(size_t)M_*D_];   // attention output        [B*S, D]
__device__ float g_tmp [(size_t)M_*D_];   // projection temp         [B*S, D]
__device__ float g_ff  [(size_t)M_*FF_];  // ff intermediate         [B*S, FF]

__device__ __forceinline__ float* buf_sel(int s) {
    switch (s) {
        case 0: return g_h;
        case 1: return g_qkv;
        case 2: return g_attn;
        case 3: return g_tmp;
        default: return g_ff;
    }
}

__device__ __forceinline__ float gelu_f(float x) {
    float x3 = x * x * x;
    return 0.5f * x * (1.0f + tanhf(0.7978845608028654f * (x + 0.044715f * x3)));
}

__device__ __forceinline__ void mma_tf32(float c[4],
                                         const unsigned a[4], const unsigned b[2]) {
    asm volatile(
        "mma.sync.aligned.m16n8k8.row.col.f32.tf32.tf32.f32 "
        "{%0,%1,%2,%3}, {%4,%5,%6,%7}, {%8,%9}, {%0,%1,%2,%3};"
        : "+f"(c[0]), "+f"(c[1]), "+f"(c[2]), "+f"(c[3])
        : "r"(a[0]), "r"(a[1]), "r"(a[2]), "r"(a[3]), "r"(b[0]), "r"(b[1]));
}

__device__ __forceinline__ void cp16(unsigned dst, const void* src) {
    asm volatile("cp.async.cg.shared.global [%0], [%1], 16;" :: "r"(dst), "l"(src));
}
__device__ __forceinline__ void cp_commit() {
    asm volatile("cp.async.commit_group;");
}

// ---------------- tensor-core GEMM: C = act(A @ B + bias) ----------------
// A: [M,K] row-major (scratch asel), B: [K,N] row-major, C: [M,N] (csel).
// Tile 128x128x16, 256 threads, warp tile 64x32, m16n8k8 tf32 fragments.
// Raw fp32 bits fed to MMA (hw truncates to tf32) -> zero cvt instructions.
// A-load mapping (verified R3): arow = tid>>2 in 0..63, akc = (tid&3)*4;
// second cp covers rows arow+64 (<=127). All smem indices in-bounds.
#define BM 128
#define BN 128
#define BKT 16
#define PADA 20
#define PADB 136

__global__ void __launch_bounds__(256) mma_gemm_kernel(
    int asel, const float* __restrict__ Bm, const float* __restrict__ bias,
    int csel, int M, int N, int K, int act)
{
    const float* __restrict__ A = buf_sel(asel);
    float* __restrict__ C = buf_sel(csel);

    __shared__ __align__(16) float As[2][BM * PADA];
    __shared__ __align__(16) float Bs[2][BKT * PADB];

    int tid = threadIdx.x;
    int lane = tid & 31;
    int warp = tid >> 5;
    int wm = (warp >> 2) * 64;    // warp m origin (0 or 64)
    int wn = (warp & 3) * 32;     // warp n origin (0,32,64,96)
    int rowBase = blockIdx.y * BM;
    int colBase = blockIdx.x * BN;

    // cp.async mapping (R3-verified)
    int arow = tid >> 2;              // 0..63
    int akc  = (tid & 3) * 4;         // 0,4,8,12
    int brow = tid >> 5;              // 0..7
    int bnc  = (tid & 31) * 4;        // 0..124

    const float* Ag = A + (size_t)(rowBase + arow) * K + akc;
    const float* Bg = Bm + (size_t)brow * N + colBase + bnc;

    unsigned sA0[2], sA1[2], sB0[2], sB1[2];
#pragma unroll
    for (int bf = 0; bf < 2; bf++) {
        sA0[bf] = (unsigned)__cvta_generic_to_shared(&As[bf][arow * PADA + akc]);
        sA1[bf] = (unsigned)__cvta_generic_to_shared(&As[bf][(arow + 64) * PADA + akc]);
        sB0[bf] = (unsigned)__cvta_generic_to_shared(&Bs[bf][brow * PADB + bnc]);
        sB1[bf] = (unsigned)__cvta_generic_to_shared(&Bs[bf][(brow + 8) * PADB + bnc]);
    }

    float c[4][4][4];
#pragma unroll
    for (int i = 0; i < 4; i++)
#pragma unroll
        for (int j = 0; j < 4; j++)
#pragma unroll
            for (int r = 0; r < 4; r++) c[i][j][r] = 0.0f;

    int nIter = K / BKT;

    // prefetch stage 0
    cp16(sA0[0], Ag);
    cp16(sA1[0], Ag + (size_t)64 * K);
    cp16(sB0[0], Bg);
    cp16(sB1[0], Bg + (size_t)8 * N);
    cp_commit();

    for (int it = 0; it < nIter; it++) {
        int cur = it & 1;
        if (it + 1 < nIter) {
            int nxt = cur ^ 1;
            const float* ap = Ag + (size_t)(it + 1) * BKT;
            const float* bp = Bg + (size_t)(it + 1) * BKT * N;
            cp16(sA0[nxt], ap);
            cp16(sA1[nxt], ap + (size_t)64 * K);
            cp16(sB0[nxt], bp);
            cp16(sB1[nxt], bp + (size_t)8 * N);
            cp_commit();
            asm volatile("cp.async.wait_group 1;");
        } else {
            asm volatile("cp.async.wait_group 0;");
        }
        __syncthreads();

        const float* as = As[cur];
        const float* bs = Bs[cur];
#pragma unroll
        for (int kk = 0; kk < BKT; kk += 8) {
            unsigned afr[4][4], bfr[4][2];
            int kc = kk + (lane & 3);
            int r0 = wm + (lane >> 2);
#pragma unroll
            for (int mf = 0; mf < 4; mf++) {
                int rw = (r0 + mf * 16) * PADA;
                afr[mf][0] = __float_as_uint(as[rw + kc]);
                afr[mf][1] = __float_as_uint(as[rw + 8 * PADA + kc]);
                afr[mf][2] = __float_as_uint(as[rw + kc + 4]);
                afr[mf][3] = __float_as_uint(as[rw + 8 * PADA + kc + 4]);
            }
            int bk0 = (kk + (lane & 3)) * PADB;
            int bn0 = wn + (lane >> 2);
#pragma unroll
            for (int nf = 0; nf < 4; nf++) {
                bfr[nf][0] = __float_as_uint(bs[bk0 + bn0 + nf * 8]);
                bfr[nf][1] = __float_as_uint(bs[bk0 + 4 * PADB + bn0 + nf * 8]);
            }
#pragma unroll
            for (int mf = 0; mf < 4; mf++)
#pragma unroll
                for (int nf = 0; nf < 4; nf++)
                    mma_tf32(c[mf][nf], afr[mf], bfr[nf]);
        }
        __syncthreads();
    }

    // epilogue: bias + optional GELU
#pragma unroll
    for (int mf = 0; mf < 4; mf++) {
        int row0 = rowBase + wm + mf * 16 + (lane >> 2);
#pragma unroll
        for (int nf = 0; nf < 4; nf++) {
            int col = colBase + wn + nf * 8 + 2 * (lane & 3);
            float b0 = bias[col], b1 = bias[col + 1];
            float v0 = c[mf][nf][0] + b0;
            float v1 = c[mf][nf][1] + b1;
            float v2 = c[mf][nf][2] + b0;
            float v3 = c[mf][nf][3] + b1;
            if (act == 1) { v0 = gelu_f(v0); v1 = gelu_f(v1); v2 = gelu_f(v2); v3 = gelu_f(v3); }
            float* p0 = C + (size_t)row0 * N + col;
            float* p1 = C + (size_t)(row0 + 8) * N + col;
            p0[0] = v0; p0[1] = v1;
            p1[0] = v2; p1[1] = v3;
        }
    }
}

// ---------------- embedding + layernorm ----------------
__global__ void __launch_bounds__(256) embed_ln_kernel(
    const int* __restrict__ ids, const float* __restrict__ emb,
    const float* __restrict__ pos, const float* __restrict__ gamma,
    const float* __restrict__ beta)
{
    int tok = blockIdx.x;
    int s = tok % S_;
    __shared__ float xs[D_];
    __shared__ float red[256];
    int t = threadIdx.x;

    int id = ids[tok];
    const float* er = emb + (size_t)id * D_;
    const float* pr = pos + (size_t)s * D_;

    float lsum = 0.0f;
    for (int d = t; d < D_; d += 256) {
        float v = er[d] + pr[d];
        xs[d] = v;
        lsum += v;
    }
    red[t] = lsum; __syncthreads();
    for (int st = 128; st > 0; st >>= 1) { if (t < st) red[t] += red[t + st]; __syncthreads(); }
    float mean = red[0] * (1.0f / D_);
    __syncthreads();

    float vs = 0.0f;
    for (int d = t; d < D_; d += 256) { float dv = xs[d] - mean; vs += dv * dv; }
    red[t] = vs; __syncthreads();
    for (int st = 128; st > 0; st >>= 1) { if (t < st) red[t] += red[t + st]; __syncthreads(); }
    float rinv = rsqrtf(red[0] * (1.0f / D_) + 1e-12f);
    __syncthreads();

    float* out = g_h + (size_t)tok * D_;
    for (int d = t; d < D_; d += 256)
        out[d] = (xs[d] - mean) * rinv * gamma[d] + beta[d];
}

// ---------------- residual add + layernorm ----------------
__global__ void __launch_bounds__(256) resid_ln_kernel(
    const float* __restrict__ gamma, const float* __restrict__ beta)
{
    int tok = blockIdx.x;
    __shared__ float xs[D_];
    __shared__ float red[256];
    int t = threadIdx.x;

    const float* hr = g_h + (size_t)tok * D_;
    const float* tr = g_tmp + (size_t)tok * D_;

    float lsum = 0.0f;
    for (int d = t; d < D_; d += 256) {
        float v = hr[d] + tr[d];
        xs[d] = v;
        lsum += v;
    }
    red[t] = lsum; __syncthreads();
    for (int st = 128; st > 0; st >>= 1) { if (t < st) red[t] += red[t + st]; __syncthreads(); }
    float mean = red[0] * (1.0f / D_);
    __syncthreads();

    float vs = 0.0f;
    for (int d = t; d < D_; d += 256) { float dv = xs[d] - mean; vs += dv * dv; }
    red[t] = vs; __syncthreads();
    for (int st = 128; st > 0; st >>= 1) { if (t < st) red[t] += red[t + st]; __syncthreads(); }
    float rinv = rsqrtf(red[0] * (1.0f / D_) + 1e-12f);
    __syncthreads();

    float* out = g_h + (size_t)tok * D_;
    for (int d = t; d < D_; d += 256)
        out[d] = (xs[d] - mean) * rinv * gamma[d] + beta[d];
}

// ---------------- block-sparse attention (256 thr: 64 rows x 4 dim-chunks) -----
__global__ void __launch_bounds__(256) attn_kernel(
    const int* __restrict__ mask, const int* __restrict__ rand_idx)
{
    __shared__ float Ks[BS_][DH_];
    __shared__ float Vs[BS_][DH_];
    __shared__ float scS[BS_][BS_ + 1];
    __shared__ float biasS[BS_];

    int nb = blockIdx.x, hh = blockIdx.y, b = blockIdx.z;
    int tid = threadIdx.x;
    int t = tid >> 2;      // query row
    int c = tid & 3;       // dim chunk (16 dims)

    int sel[NSEL_];
    sel[0] = 0;
    sel[1] = (nb + NB_ - 1) % NB_;
    sel[2] = nb;
    sel[3] = (nb + 1) % NB_;
    sel[4] = NB_ - 1;
    sel[5] = rand_idx[nb * R_ + 0];
    sel[6] = rand_idx[nb * R_ + 1];
    sel[7] = rand_idx[nb * R_ + 2];

    const float scale = 0.125f;
    float q[16], o[16];
    const float* qrow = g_qkv + (size_t)(b * S_ + nb * BS_ + t) * D3_ + hh * DH_ + c * 16;
#pragma unroll
    for (int d = 0; d < 16; d++) { q[d] = qrow[d] * scale; o[d] = 0.0f; }

    float mx = -1e30f, lsum = 0.0f;

    for (int sblk = 0; sblk < NSEL_; sblk++) {
        int kb = sel[sblk];
        size_t kbase = (size_t)(b * S_ + kb * BS_) * D3_ + D_ + hh * DH_;
        size_t vbase = kbase + D_;

#pragma unroll
        for (int i = 0; i < 16; i++) {
            int idx = tid + i * 256;
            int r = idx >> 6, dc = idx & 63;
            Ks[r][dc] = g_qkv[kbase + (size_t)r * D3_ + dc];
            Vs[r][dc] = g_qkv[vbase + (size_t)r * D3_ + dc];
        }
        if (tid < BS_) biasS[tid] = (mask[b * S_ + kb * BS_ + tid] > 0) ? 0.0f : -1e9f;
        __syncthreads();

        float bm = -1e30f;
        for (int j = 0; j < BS_; j++) {
            const float4* kr = (const float4*)&Ks[j][c * 16];
            float4 k0 = kr[0], k1 = kr[1], k2 = kr[2], k3 = kr[3];
            float s = q[0]*k0.x + q[1]*k0.y + q[2]*k0.z + q[3]*k0.w
                    + q[4]*k1.x + q[5]*k1.y + q[6]*k1.z + q[7]*k1.w
                    + q[8]*k2.x + q[9]*k2.y + q[10]*k2.z + q[11]*k2.w
                    + q[12]*k3.x + q[13]*k3.y + q[14]*k3.z + q[15]*k3.w;
            s += __shfl_xor_sync(0xffffffffu, s, 1);
            s += __shfl_xor_sync(0xffffffffu, s, 2);
            s += biasS[j];
            if (c == 0) scS[j][t] = s;
            bm = fmaxf(bm, s);
        }
        __syncwarp();

        float mnew = fmaxf(mx, bm);
        float corr = __expf(mx - mnew);
        lsum *= corr;
#pragma unroll
        for (int d = 0; d < 16; d++) o[d] *= corr;

        for (int j = 0; j < BS_; j++) {
            float p = __expf(scS[j][t] - mnew);
            lsum += p;
            const float4* vr = (const float4*)&Vs[j][c * 16];
            float4 v0 = vr[0], v1 = vr[1], v2 = vr[2], v3 = vr[3];
            o[0] += p*v0.x;  o[1] += p*v0.y;  o[2] += p*v0.z;  o[3] += p*v0.w;
            o[4] += p*v1.x;  o[5] += p*v1.y;  o[6] += p*v1.z;  o[7] += p*v1.w;
            o[8] += p*v2.x;  o[9] += p*v2.y;  o[10] += p*v2.z; o[11] += p*v2.w;
            o[12] += p*v3.x; o[13] += p*v3.y; o[14] += p*v3.z; o[15] += p*v3.w;
        }
        mx = mnew;
        __syncthreads();
    }

    float inv = 1.0f / lsum;
    float* outp = g_attn + (size_t)(b * S_ + nb * BS_ + t) * D_ + hh * DH_ + c * 16;
#pragma unroll
    for (int d = 0; d < 16; d += 4) {
        float4 v = make_float4(o[d] * inv, o[d+1] * inv, o[d+2] * inv, o[d+3] * inv);
        *(float4*)(outp + d) = v;
    }
}

// ---------------- pooler + classifier + loss ----------------
__global__ void __launch_bounds__(256) head_kernel(
    const float* __restrict__ Wp, const float* __restrict__ bp,
    const float* __restrict__ Wc, const float* __restrict__ bc,
    const int* __restrict__ label, float* __restrict__ out, int out_size)
{
    __shared__ float pooled[B_][D_];
    int t = threadIdx.x;

    for (int b = 0; b < B_; b++) {
        const float* x = g_h + (size_t)b * S_ * D_;
        for (int j = t; j < D_; j += 256) {
            float acc = bp[j];
            for (int d = 0; d < D_; d++) acc += x[d] * Wp[(size_t)d * D_ + j];
            pooled[b][j] = tanhf(acc);
        }
    }
    __syncthreads();

    if (t == 0) {
        float loss = 0.0f;
        for (int b = 0; b < B_; b++) {
            float lg0 = bc[0], lg1 = bc[1];
            for (int j = 0; j < D_; j++) {
                float pv = pooled[b][j];
                lg0 += pv * Wc[j * 2 + 0];
                lg1 += pv * Wc[j * 2 + 1];
            }
            float m = fmaxf(lg0, lg1);
            float e0 = expf(lg0 - m), e1 = expf(lg1 - m);
            float sinv = 1.0f / (e0 + e1);
            float p0 = e0 * sinv, p1 = e1 * sinv;
            out[b * 2 + 0] = p0;
            out[b * 2 + 1] = p1;
            float mm = fmaxf(p0, p1);
            float z = logf(expf(p0 - mm) + expf(p1 - mm)) + mm;
            float lp = ((label[b] == 0) ? p0 : p1) - z;
            loss += -lp;
        }
        loss *= (1.0f / B_);
        if (out_size > B_ * 2) out[B_ * 2] = loss;
    }
}

// ---------------- launch ----------------
extern "C" void kernel_launch(void* const* d_in, const int* in_sizes, int n_in,
                              void* d_out, int out_size)
{
    const int*   input_ids = (const int*)d_in[0];
    const int*   attn_mask = (const int*)d_in[1];
    const int*   label     = (const int*)d_in[2];
    const int*   rand_idx  = (const int*)d_in[3];
    const float* emb   = (const float*)d_in[4];
    const float* pos   = (const float*)d_in[5];
    const float* lng   = (const float*)d_in[6];
    const float* lnb   = (const float*)d_in[7];
    const float* Wqkv  = (const float*)d_in[8];
    const float* bqkv  = (const float*)d_in[9];
    const float* Wo    = (const float*)d_in[10];
    const float* bo    = (const float*)d_in[11];
    const float* ln1g  = (const float*)d_in[12];
    const float* ln1b  = (const float*)d_in[13];
    const float* Wff1  = (const float*)d_in[14];
    const float* bff1  = (const float*)d_in[15];
    const float* Wff2  = (const float*)d_in[16];
    const float* bff2  = (const float*)d_in[17];
    const float* ln2g  = (const float*)d_in[18];
    const float* ln2b  = (const float*)d_in[19];
    const float* Wp    = (const float*)d_in[20];
    const float* bp    = (const float*)d_in[21];
    const float* Wc    = (const float*)d_in[22];
    const float* bc    = (const float*)d_in[23];

    embed_ln_kernel<<<M_, 256>>>(input_ids, emb, pos, lng, lnb);

    for (int l = 0; l < L_; l++) {
        mma_gemm_kernel<<<dim3(D3_ / BN, M_ / BM), 256>>>(
            0, Wqkv + (size_t)l * D_ * D3_, bqkv + (size_t)l * D3_, 1, M_, D3_, D_, 0);
        attn_kernel<<<dim3(NB_, H_, B_), 256>>>(attn_mask, rand_idx);
        mma_gemm_kernel<<<dim3(D_ / BN, M_ / BM), 256>>>(
            2, Wo + (size_t)l * D_ * D_, bo + (size_t)l * D_, 3, M_, D_, D_, 0);
        resid_ln_kernel<<<M_, 256>>>(ln1g + (size_t)l * D_, ln1b + (size_t)l * D_);
        mma_gemm_kernel<<<dim3(FF_ / BN, M_ / BM), 256>>>(
            0, Wff1 + (size_t)l * D_ * FF_, bff1 + (size_t)l * FF_, 4, M_, FF_, D_, 1);
        mma_gemm_kernel<<<dim3(D_ / BN, M_ / BM), 256>>>(
            4, Wff2 + (size_t)l * FF_ * D_, bff2 + (size_t)l * D_, 3, M_, D_, FF_, 0);
        resid_ln_kernel<<<M_, 256>>>(ln2g + (size_t)l * D_, ln2b + (size_t)l * D_);
    }

    head_kernel<<<1, 256>>>(Wp, bp, Wc, bc, label, (float*)d_out, out_size);
}

// round 13
// speedup vs baseline: 1.7783x; 1.7783x over previous
#include <cuda_runtime.h>
#include <math.h>

#define B_   4
#define S_   4096
#define D_   768
#define H_   12
#define DH_  64
#define BS_  64
#define L_   2
#define R_   3
#define FF_  3072
#define NB_  64
#define NSEL_ 8
#define D3_  2304
#define M_   (B_*S_)

// ---------------- scratch (static device globals; no allocation) ----------------
__device__ float g_h   [(size_t)M_*D_];   // hidden state            [B*S, D]
__device__ float g_qkv [(size_t)M_*D3_];  // qkv projection          [B*S, 3D]
__device__ float g_attn[(size_t)M_*D_];   // attention output        [B*S, D]
__device__ float g_tmp [(size_t)M_*D_];   // projection temp         [B*S, D]
__device__ float g_ff  [(size_t)M_*FF_];  // ff intermediate         [B*S, FF]

__device__ __forceinline__ float* buf_sel(int s) {
    switch (s) {
        case 0: return g_h;
        case 1: return g_qkv;
        case 2: return g_attn;
        case 3: return g_tmp;
        default: return g_ff;
    }
}

__device__ __forceinline__ float gelu_f(float x) {
    float x3 = x * x * x;
    return 0.5f * x * (1.0f + tanhf(0.7978845608028654f * (x + 0.044715f * x3)));
}

__device__ __forceinline__ void mma_tf32(float c[4],
                                         const unsigned a[4], const unsigned b[2]) {
    asm volatile(
        "mma.sync.aligned.m16n8k8.row.col.f32.tf32.tf32.f32 "
        "{%0,%1,%2,%3}, {%4,%5,%6,%7}, {%8,%9}, {%0,%1,%2,%3};"
        : "+f"(c[0]), "+f"(c[1]), "+f"(c[2]), "+f"(c[3])
        : "r"(a[0]), "r"(a[1]), "r"(a[2]), "r"(a[3]), "r"(b[0]), "r"(b[1]));
}

__device__ __forceinline__ void cp16(unsigned dst, const void* src) {
    asm volatile("cp.async.cg.shared.global [%0], [%1], 16;" :: "r"(dst), "l"(src));
}
__device__ __forceinline__ void cp_commit() {
    asm volatile("cp.async.commit_group;");
}

// ---------------- tensor-core GEMM: C = act(A @ B + bias) ----------------
// A: [M,K] row-major (scratch asel), B: [K,N] row-major, C: [M,N] (csel).
// Tile 128x128x16, 128 threads (4 warps), warp tile 64x64, m16n8k8 tf32.
// Raw fp32 bits fed to MMA (hw truncates to tf32) -> zero cvt instructions.
// LDS:MMA ratio 1.0 (32 scalar LDS feed 32 MMAs per warp-k8).
#define BM 128
#define BN 128
#define BKT 16
#define PADA 20
#define PADB 136

__global__ void __launch_bounds__(128) mma_gemm_kernel(
    int asel, const float* __restrict__ Bm, const float* __restrict__ bias,
    int csel, int M, int N, int K, int act)
{
    const float* __restrict__ A = buf_sel(asel);
    float* __restrict__ C = buf_sel(csel);

    __shared__ __align__(16) float As[2][BM * PADA];
    __shared__ __align__(16) float Bs[2][BKT * PADB];

    int tid = threadIdx.x;
    int lane = tid & 31;
    int warp = tid >> 5;                // 0..3
    int wm = (warp & 1) * 64;           // warp m origin (0 or 64)
    int wn = (warp >> 1) * 64;          // warp n origin (0 or 64)
    int rowBase = blockIdx.y * BM;
    int colBase = blockIdx.x * BN;

    // cp.async mapping (128 threads, 4 float4 each for A and for B)
    int arow = tid >> 2;                // 0..31 (rows arow, +32, +64, +96)
    int akc  = (tid & 3) * 4;           // 0,4,8,12
    int brow = tid >> 5;                // 0..3 (rows brow, +4, +8, +12)
    int bnc  = (tid & 31) * 4;          // 0..124

    const float* Ag = A + (size_t)(rowBase + arow) * K + akc;
    const float* Bg = Bm + (size_t)brow * N + colBase + bnc;

    unsigned sA[2][4], sB[2][4];
#pragma unroll
    for (int bf = 0; bf < 2; bf++) {
#pragma unroll
        for (int i = 0; i < 4; i++) {
            sA[bf][i] = (unsigned)__cvta_generic_to_shared(&As[bf][(arow + i * 32) * PADA + akc]);
            sB[bf][i] = (unsigned)__cvta_generic_to_shared(&Bs[bf][(brow + i * 4) * PADB + bnc]);
        }
    }

    float c[4][8][4];
#pragma unroll
    for (int i = 0; i < 4; i++)
#pragma unroll
        for (int j = 0; j < 8; j++)
#pragma unroll
            for (int r = 0; r < 4; r++) c[i][j][r] = 0.0f;

    int nIter = K / BKT;

    // prefetch stage 0
#pragma unroll
    for (int i = 0; i < 4; i++) {
        cp16(sA[0][i], Ag + (size_t)(i * 32) * K);
        cp16(sB[0][i], Bg + (size_t)(i * 4) * N);
    }
    cp_commit();

    for (int it = 0; it < nIter; it++) {
        int cur = it & 1;
        if (it + 1 < nIter) {
            int nxt = cur ^ 1;
            const float* ap = Ag + (size_t)(it + 1) * BKT;
            const float* bp = Bg + (size_t)(it + 1) * BKT * N;
#pragma unroll
            for (int i = 0; i < 4; i++) {
                cp16(sA[nxt][i], ap + (size_t)(i * 32) * K);
                cp16(sB[nxt][i], bp + (size_t)(i * 4) * N);
            }
            cp_commit();
            asm volatile("cp.async.wait_group 1;");
        } else {
            asm volatile("cp.async.wait_group 0;");
        }
        __syncthreads();

        const float* as = As[cur];
        const float* bs = Bs[cur];
#pragma unroll
        for (int kk = 0; kk < BKT; kk += 8) {
            unsigned afr[4][4], bfr[8][2];
            int kc = kk + (lane & 3);
            int r0 = wm + (lane >> 2);
#pragma unroll
            for (int mf = 0; mf < 4; mf++) {
                int rw = (r0 + mf * 16) * PADA;
                afr[mf][0] = __float_as_uint(as[rw + kc]);
                afr[mf][1] = __float_as_uint(as[rw + 8 * PADA + kc]);
                afr[mf][2] = __float_as_uint(as[rw + kc + 4]);
                afr[mf][3] = __float_as_uint(as[rw + 8 * PADA + kc + 4]);
            }
            int bk0 = (kk + (lane & 3)) * PADB;
            int bn0 = wn + (lane >> 2);
#pragma unroll
            for (int nf = 0; nf < 8; nf++) {
                bfr[nf][0] = __float_as_uint(bs[bk0 + bn0 + nf * 8]);
                bfr[nf][1] = __float_as_uint(bs[bk0 + 4 * PADB + bn0 + nf * 8]);
            }
#pragma unroll
            for (int mf = 0; mf < 4; mf++)
#pragma unroll
                for (int nf = 0; nf < 8; nf++)
                    mma_tf32(c[mf][nf], afr[mf], bfr[nf]);
        }
        __syncthreads();
    }

    // epilogue: bias + optional GELU
#pragma unroll
    for (int mf = 0; mf < 4; mf++) {
        int row0 = rowBase + wm + mf * 16 + (lane >> 2);
#pragma unroll
        for (int nf = 0; nf < 8; nf++) {
            int col = colBase + wn + nf * 8 + 2 * (lane & 3);
            float b0 = bias[col], b1 = bias[col + 1];
            float v0 = c[mf][nf][0] + b0;
            float v1 = c[mf][nf][1] + b1;
            float v2 = c[mf][nf][2] + b0;
            float v3 = c[mf][nf][3] + b1;
            if (act == 1) { v0 = gelu_f(v0); v1 = gelu_f(v1); v2 = gelu_f(v2); v3 = gelu_f(v3); }
            float* p0 = C + (size_t)row0 * N + col;
            float* p1 = C + (size_t)(row0 + 8) * N + col;
            p0[0] = v0; p0[1] = v1;
            p1[0] = v2; p1[1] = v3;
        }
    }
}

// ---------------- embedding + layernorm ----------------
__global__ void __launch_bounds__(256) embed_ln_kernel(
    const int* __restrict__ ids, const float* __restrict__ emb,
    const float* __restrict__ pos, const float* __restrict__ gamma,
    const float* __restrict__ beta)
{
    int tok = blockIdx.x;
    int s = tok % S_;
    __shared__ float xs[D_];
    __shared__ float red[256];
    int t = threadIdx.x;

    int id = ids[tok];
    const float* er = emb + (size_t)id * D_;
    const float* pr = pos + (size_t)s * D_;

    float lsum = 0.0f;
    for (int d = t; d < D_; d += 256) {
        float v = er[d] + pr[d];
        xs[d] = v;
        lsum += v;
    }
    red[t] = lsum; __syncthreads();
    for (int st = 128; st > 0; st >>= 1) { if (t < st) red[t] += red[t + st]; __syncthreads(); }
    float mean = red[0] * (1.0f / D_);
    __syncthreads();

    float vs = 0.0f;
    for (int d = t; d < D_; d += 256) { float dv = xs[d] - mean; vs += dv * dv; }
    red[t] = vs; __syncthreads();
    for (int st = 128; st > 0; st >>= 1) { if (t < st) red[t] += red[t + st]; __syncthreads(); }
    float rinv = rsqrtf(red[0] * (1.0f / D_) + 1e-12f);
    __syncthreads();

    float* out = g_h + (size_t)tok * D_;
    for (int d = t; d < D_; d += 256)
        out[d] = (xs[d] - mean) * rinv * gamma[d] + beta[d];
}

// ---------------- residual add + layernorm ----------------
__global__ void __launch_bounds__(256) resid_ln_kernel(
    const float* __restrict__ gamma, const float* __restrict__ beta)
{
    int tok = blockIdx.x;
    __shared__ float xs[D_];
    __shared__ float red[256];
    int t = threadIdx.x;

    const float* hr = g_h + (size_t)tok * D_;
    const float* tr = g_tmp + (size_t)tok * D_;

    float lsum = 0.0f;
    for (int d = t; d < D_; d += 256) {
        float v = hr[d] + tr[d];
        xs[d] = v;
        lsum += v;
    }
    red[t] = lsum; __syncthreads();
    for (int st = 128; st > 0; st >>= 1) { if (t < st) red[t] += red[t + st]; __syncthreads(); }
    float mean = red[0] * (1.0f / D_);
    __syncthreads();

    float vs = 0.0f;
    for (int d = t; d < D_; d += 256) { float dv = xs[d] - mean; vs += dv * dv; }
    red[t] = vs; __syncthreads();
    for (int st = 128; st > 0; st >>= 1) { if (t < st) red[t] += red[t + st]; __syncthreads(); }
    float rinv = rsqrtf(red[0] * (1.0f / D_) + 1e-12f);
    __syncthreads();

    float* out = g_h + (size_t)tok * D_;
    for (int d = t; d < D_; d += 256)
        out[d] = (xs[d] - mean) * rinv * gamma[d] + beta[d];
}

// ---------------- block-sparse attention (64 threads, proven R3 version) ------
__global__ void __launch_bounds__(64) attn_kernel(
    const int* __restrict__ mask, const int* __restrict__ rand_idx)
{
    __shared__ float KV[BS_][DH_];        // K tile, then reused for V tile
    __shared__ float scS[BS_][BS_ + 1];   // scS[j][t] = score(row t, key j)
    __shared__ float biasS[BS_];

    int nb = blockIdx.x, hh = blockIdx.y, b = blockIdx.z;
    int t = threadIdx.x;

    int sel[NSEL_];
    sel[0] = 0;
    sel[1] = (nb + NB_ - 1) % NB_;
    sel[2] = nb;
    sel[3] = (nb + 1) % NB_;
    sel[4] = NB_ - 1;
    sel[5] = rand_idx[nb * R_ + 0];
    sel[6] = rand_idx[nb * R_ + 1];
    sel[7] = rand_idx[nb * R_ + 2];

    const float scale = 0.125f;
    float q[DH_], o[DH_];
    const float* qrow = g_qkv + (size_t)(b * S_ + nb * BS_ + t) * D3_ + hh * DH_;
#pragma unroll
    for (int d = 0; d < DH_; d++) { q[d] = qrow[d] * scale; o[d] = 0.0f; }

    float mx = -1e30f, lsum = 0.0f;

    for (int sblk = 0; sblk < NSEL_; sblk++) {
        int kb = sel[sblk];
        size_t kbase = (size_t)(b * S_ + kb * BS_) * D3_ + D_ + hh * DH_;

        for (int r = 0; r < BS_; r++)
            KV[r][t] = g_qkv[kbase + (size_t)r * D3_ + t];
        biasS[t] = (mask[b * S_ + kb * BS_ + t] > 0) ? 0.0f : -1e9f;
        __syncthreads();

        float bm = -1e30f;
        for (int j = 0; j < BS_; j++) {
            float sacc = 0.0f;
#pragma unroll
            for (int d = 0; d < DH_; d++) sacc += q[d] * KV[j][d];
            sacc += biasS[j];
            scS[j][t] = sacc;
            bm = fmaxf(bm, sacc);
        }
        __syncthreads();

        size_t vbase = kbase + D_;
        for (int r = 0; r < BS_; r++)
            KV[r][t] = g_qkv[vbase + (size_t)r * D3_ + t];

        float mnew = fmaxf(mx, bm);
        float corr = __expf(mx - mnew);
        lsum *= corr;
#pragma unroll
        for (int d = 0; d < DH_; d++) o[d] *= corr;
        __syncthreads();

        for (int j = 0; j < BS_; j++) {
            float p = __expf(scS[j][t] - mnew);
            lsum += p;
#pragma unroll
            for (int d = 0; d < DH_; d++) o[d] += p * KV[j][d];
        }
        mx = mnew;
        __syncthreads();
    }

    float inv = 1.0f / lsum;
#pragma unroll
    for (int d = 0; d < DH_; d++) scS[t][d] = o[d] * inv;
    __syncthreads();
    for (int r = 0; r < BS_; r++)
        g_attn[(size_t)(b * S_ + nb * BS_ + r) * D_ + hh * DH_ + t] = scS[r][t];
}

// ---------------- pooler + classifier + loss ----------------
__global__ void __launch_bounds__(256) head_kernel(
    const float* __restrict__ Wp, const float* __restrict__ bp,
    const float* __restrict__ Wc, const float* __restrict__ bc,
    const int* __restrict__ label, float* __restrict__ out, int out_size)
{
    __shared__ float pooled[B_][D_];
    int t = threadIdx.x;

    for (int b = 0; b < B_; b++) {
        const float* x = g_h + (size_t)b * S_ * D_;
        for (int j = t; j < D_; j += 256) {
            float acc = bp[j];
            for (int d = 0; d < D_; d++) acc += x[d] * Wp[(size_t)d * D_ + j];
            pooled[b][j] = tanhf(acc);
        }
    }
    __syncthreads();

    if (t == 0) {
        float loss = 0.0f;
        for (int b = 0; b < B_; b++) {
            float lg0 = bc[0], lg1 = bc[1];
            for (int j = 0; j < D_; j++) {
                float pv = pooled[b][j];
                lg0 += pv * Wc[j * 2 + 0];
                lg1 += pv * Wc[j * 2 + 1];
            }
            float m = fmaxf(lg0, lg1);
            float e0 = expf(lg0 - m), e1 = expf(lg1 - m);
            float sinv = 1.0f / (e0 + e1);
            float p0 = e0 * sinv, p1 = e1 * sinv;
            out[b * 2 + 0] = p0;
            out[b * 2 + 1] = p1;
            float mm = fmaxf(p0, p1);
            float z = logf(expf(p0 - mm) + expf(p1 - mm)) + mm;
            float lp = ((label[b] == 0) ? p0 : p1) - z;
            loss += -lp;
        }
        loss *= (1.0f / B_);
        if (out_size > B_ * 2) out[B_ * 2] = loss;
    }
}

// ---------------- launch ----------------
extern "C" void kernel_launch(void* const* d_in, const int* in_sizes, int n_in,
                              void* d_out, int out_size)
{
    const int*   input_ids = (const int*)d_in[0];
    const int*   attn_mask = (const int*)d_in[1];
    const int*   label     = (const int*)d_in[2];
    const int*   rand_idx  = (const int*)d_in[3];
    const float* emb   = (const float*)d_in[4];
    const float* pos   = (const float*)d_in[5];
    const float* lng   = (const float*)d_in[6];
    const float* lnb   = (const float*)d_in[7];
    const float* Wqkv  = (const float*)d_in[8];
    const float* bqkv  = (const float*)d_in[9];
    const float* Wo    = (const float*)d_in[10];
    const float* bo    = (const float*)d_in[11];
    const float* ln1g  = (const float*)d_in[12];
    const float* ln1b  = (const float*)d_in[13];
    const float* Wff1  = (const float*)d_in[14];
    const float* bff1  = (const float*)d_in[15];
    const float* Wff2  = (const float*)d_in[16];
    const float* bff2  = (const float*)d_in[17];
    const float* ln2g  = (const float*)d_in[18];
    const float* ln2b  = (const float*)d_in[19];
    const float* Wp    = (const float*)d_in[20];
    const float* bp    = (const float*)d_in[21];
    const float* Wc    = (const float*)d_in[22];
    const float* bc    = (const float*)d_in[23];

    embed_ln_kernel<<<M_, 256>>>(input_ids, emb, pos, lng, lnb);

    for (int l = 0; l < L_; l++) {
        mma_gemm_kernel<<<dim3(D3_ / BN, M_ / BM), 128>>>(
            0, Wqkv + (size_t)l * D_ * D3_, bqkv + (size_t)l * D3_, 1, M_, D3_, D_, 0);
        attn_kernel<<<dim3(NB_, H_, B_), 64>>>(attn_mask, rand_idx);
        mma_gemm_kernel<<<dim3(D_ / BN, M_ / BM), 128>>>(
            2, Wo + (size_t)l * D_ * D_, bo + (size_t)l * D_, 3, M_, D_, D_, 0);
        resid_ln_kernel<<<M_, 256>>>(ln1g + (size_t)l * D_, ln1b + (size_t)l * D_);
        mma_gemm_kernel<<<dim3(FF_ / BN, M_ / BM), 128>>>(
            0, Wff1 + (size_t)l * D_ * FF_, bff1 + (size_t)l * FF_, 4, M_, FF_, D_, 1);
        mma_gemm_kernel<<<dim3(D_ / BN, M_ / BM), 128>>>(
            4, Wff2 + (size_t)l * FF_ * D_, bff2 + (size_t)l * D_, 3, M_, D_, FF_, 0);
        resid_ln_kernel<<<M_, 256>>>(ln2g + (size_t)l * D_, ln2b + (size_t)l * D_);
    }

    head_kernel<<<1, 256>>>(Wp, bp, Wc, bc, label, (float*)d_out, out_size);
}